// round 16
// baseline (speedup 1.0000x reference)
#include <cuda_runtime.h>
#include <cuda_bf16.h>
#include <stdint.h>

// out[token, :] = sign(weight[id, :]) * max(scales[id, col/128], 1e-8)
// ids: int32 [16384], weight: f32 [50257,1024], scales: f32 [50257,8]
//
// FINAL (best measured 18.59us; re-bench 18.9, 19.2 -> mean ~18.9 +/- 0.3).
// Warp-private cp.async pipeline: each warp owns a 2-stage ring of 4KB row
// buffers; no __syncthreads in the loop. cp.async.cg bypasses L1; each lane
// reads back exactly the smem bytes its own cp.async wrote, so only the
// tiny scale buffer needs __syncwarp. __stcs streaming stores evict output
// from L2 early so the ~56MB of unique weight rows stay L2-resident across
// graph replays (verified: .wb / ldcs variants regress 2-4us).
//
// Roofline (15 designs tested): 128MB/launch must cross the LTS (64MB
// weight reads + 64MB output writes, both algorithmically minimal for this
// problem); 128MB / 18.6us ~= 6.9TB/s ~= the path-independent LTS
// structural cap, and the 64MB DRAM write stream alone sets ~17.3us.
// This kernel sits on that wall.

#define DIM       1024
#define NGROUP    8
#define THREADS   128
#define NW        4          // warps per block
#define DEPTH     2          // pipeline stages per warp
#define RPW       8          // rows (tokens) per warp
#define TPB       (NW * RPW) // 32 tokens per block

__global__ __launch_bounds__(THREADS)
void literati_embed_kernel(const int* __restrict__ ids,
                           const float* __restrict__ weight,
                           const float* __restrict__ scales,
                           float* __restrict__ out,
                           int n_tokens)
{
    __shared__ __align__(16) float wbuf[NW][DEPTH][DIM];     // 32 KB
    __shared__ __align__(16) float sbuf[NW][DEPTH][NGROUP];  // 256 B
    __shared__ int srows[TPB];

    const int t    = threadIdx.x;
    const int wid  = t >> 5;
    const int ln   = t & 31;
    const int tok0 = blockIdx.x * TPB;

    if (t < TPB) {
        int tok = tok0 + t;
        srows[t] = (tok < n_tokens) ? ids[tok] : 0;
    }
    __syncthreads();  // only block-wide sync

    auto issue = [&](int r) {
        if (r < RPW) {
            const int stage = r & (DEPTH - 1);
            const int row   = srows[wid * RPW + r];
            const float* src = weight + (size_t)row * DIM;
#pragma unroll
            for (int j = 0; j < 8; j++) {
                uint32_t dst = (uint32_t)__cvta_generic_to_shared(
                    &wbuf[wid][stage][j * 128 + ln * 4]);
                asm volatile("cp.async.cg.shared.global [%0], [%1], 16;\n"
                             :: "r"(dst), "l"(src + j * 128 + ln * 4));
            }
            if (ln < 2) {
                uint32_t dst = (uint32_t)__cvta_generic_to_shared(
                    &sbuf[wid][stage][ln * 4]);
                asm volatile("cp.async.cg.shared.global [%0], [%1], 16;\n"
                             :: "r"(dst), "l"(scales + (size_t)row * NGROUP + ln * 4));
            }
        }
        asm volatile("cp.async.commit_group;\n");
    };

#pragma unroll
    for (int r = 0; r < DEPTH; r++) issue(r);

    for (int r = 0; r < RPW; r++) {
        asm volatile("cp.async.wait_group %0;\n" :: "n"(DEPTH - 1));
        __syncwarp();  // make lane0/1's sbuf visible to all lanes

        const int stage = r & (DEPTH - 1);
        const int tok   = tok0 + wid * RPW + r;
        float4* orow = reinterpret_cast<float4*>(out + (size_t)tok * DIM);

#pragma unroll
        for (int j = 0; j < 8; j++) {
            float s = fmaxf(sbuf[wid][stage][j], 1e-8f);  // broadcast
            float4 w = *reinterpret_cast<const float4*>(
                &wbuf[wid][stage][j * 128 + ln * 4]);
            float4 o;
            o.x = (w.x < 0.0f) ? -s : s;
            o.y = (w.y < 0.0f) ? -s : s;
            o.z = (w.z < 0.0f) ? -s : s;
            o.w = (w.w < 0.0f) ? -s : s;
            if (tok < n_tokens)
                __stcs(&orow[j * 32 + ln], o);
        }

        __syncwarp();
        issue(r + DEPTH);
    }
}

extern "C" void kernel_launch(void* const* d_in, const int* in_sizes, int n_in,
                              void* d_out, int out_size)
{
    const int* ids      = (const int*)d_in[0];
    const float* weight = (const float*)d_in[1];
    const float* scales = (const float*)d_in[2];
    float* out          = (float*)d_out;

    const int n_tokens = in_sizes[0];  // 16384
    const int blocks = (n_tokens + TPB - 1) / TPB;

    literati_embed_kernel<<<blocks, THREADS>>>(ids, weight, scales, out, n_tokens);
}

// round 17
// speedup vs baseline: 1.0345x; 1.0345x over previous
#include <cuda_runtime.h>
#include <cuda_bf16.h>
#include <stdint.h>

// out[token, :] = sign(weight[id, :]) * max(scales[id, col/128], 1e-8)
// ids: int32 [16384], weight: f32 [50257,1024], scales: f32 [50257,8]
//
// FINAL. Best measured 18.59us; identical-binary re-benches 18.9/19.2/19.2
// (mean ~18.9 +/- 0.3us run-to-run variance).
//
// Warp-private cp.async pipeline: each warp owns a 2-stage ring of 4KB row
// buffers; no __syncthreads in the loop. cp.async.cg bypasses L1; each lane
// reads back exactly the smem bytes its own cp.async wrote, so only the
// tiny scale buffer needs __syncwarp. __stcs streaming stores evict output
// from L2 early so the ~56MB of unique weight rows stay L2-resident across
// graph replays (measured: .wb / ldcs / ldcg variants regress 2-4us).
//
// Roofline (16 rounds, 13 distinct designs): 128MB/launch must cross the
// LTS (64MB weight reads + 64MB output writes, both algorithmically
// minimal); 128MB / 18.6us ~= 6.9TB/s ~= the path-independent LTS
// structural cap, and the 64MB DRAM write stream alone sets ~17.3us.
// This kernel sits on that wall; SM-side restructuring is flat within
// variance once traffic and cache policy are right.

#define DIM       1024
#define NGROUP    8
#define THREADS   128
#define NW        4          // warps per block
#define DEPTH     2          // pipeline stages per warp
#define RPW       8          // rows (tokens) per warp
#define TPB       (NW * RPW) // 32 tokens per block

__global__ __launch_bounds__(THREADS)
void literati_embed_kernel(const int* __restrict__ ids,
                           const float* __restrict__ weight,
                           const float* __restrict__ scales,
                           float* __restrict__ out,
                           int n_tokens)
{
    __shared__ __align__(16) float wbuf[NW][DEPTH][DIM];     // 32 KB
    __shared__ __align__(16) float sbuf[NW][DEPTH][NGROUP];  // 256 B
    __shared__ int srows[TPB];

    const int t    = threadIdx.x;
    const int wid  = t >> 5;
    const int ln   = t & 31;
    const int tok0 = blockIdx.x * TPB;

    if (t < TPB) {
        int tok = tok0 + t;
        srows[t] = (tok < n_tokens) ? ids[tok] : 0;
    }
    __syncthreads();  // only block-wide sync

    auto issue = [&](int r) {
        if (r < RPW) {
            const int stage = r & (DEPTH - 1);
            const int row   = srows[wid * RPW + r];
            const float* src = weight + (size_t)row * DIM;
#pragma unroll
            for (int j = 0; j < 8; j++) {
                uint32_t dst = (uint32_t)__cvta_generic_to_shared(
                    &wbuf[wid][stage][j * 128 + ln * 4]);
                asm volatile("cp.async.cg.shared.global [%0], [%1], 16;\n"
                             :: "r"(dst), "l"(src + j * 128 + ln * 4));
            }
            if (ln < 2) {
                uint32_t dst = (uint32_t)__cvta_generic_to_shared(
                    &sbuf[wid][stage][ln * 4]);
                asm volatile("cp.async.cg.shared.global [%0], [%1], 16;\n"
                             :: "r"(dst), "l"(scales + (size_t)row * NGROUP + ln * 4));
            }
        }
        asm volatile("cp.async.commit_group;\n");
    };

#pragma unroll
    for (int r = 0; r < DEPTH; r++) issue(r);

    for (int r = 0; r < RPW; r++) {
        asm volatile("cp.async.wait_group %0;\n" :: "n"(DEPTH - 1));
        __syncwarp();  // make lane0/1's sbuf visible to all lanes

        const int stage = r & (DEPTH - 1);
        const int tok   = tok0 + wid * RPW + r;
        float4* orow = reinterpret_cast<float4*>(out + (size_t)tok * DIM);

#pragma unroll
        for (int j = 0; j < 8; j++) {
            float s = fmaxf(sbuf[wid][stage][j], 1e-8f);  // broadcast
            float4 w = *reinterpret_cast<const float4*>(
                &wbuf[wid][stage][j * 128 + ln * 4]);
            float4 o;
            o.x = (w.x < 0.0f) ? -s : s;
            o.y = (w.y < 0.0f) ? -s : s;
            o.z = (w.z < 0.0f) ? -s : s;
            o.w = (w.w < 0.0f) ? -s : s;
            if (tok < n_tokens)
                __stcs(&orow[j * 32 + ln], o);
        }

        __syncwarp();
        issue(r + DEPTH);
    }
}

extern "C" void kernel_launch(void* const* d_in, const int* in_sizes, int n_in,
                              void* d_out, int out_size)
{
    const int* ids      = (const int*)d_in[0];
    const float* weight = (const float*)d_in[1];
    const float* scales = (const float*)d_in[2];
    float* out          = (float*)d_out;

    const int n_tokens = in_sizes[0];  // 16384
    const int blocks = (n_tokens + TPB - 1) / TPB;

    literati_embed_kernel<<<blocks, THREADS>>>(ids, weight, scales, out, n_tokens);
}